// round 10
// baseline (speedup 1.0000x reference)
#include <cuda_runtime.h>
#include <cuda_fp16.h>
#include <math.h>
#include <stdint.h>
#include <mma.h>

using namespace nvcuda;

#define NTOK 8192
#define HD   1024
#define NT   3
#define NE   6
#define NB   128
#define NC   64

// GEMM tiling (fp16 inputs, fp32 accumulate)
#define BM 128
#define BN 128
#define BK 64
#define KT (HD / BK)
#define LDA 72                        // 64 + 8 halves pad
#define LDB 136                       // 128 + 8 halves pad
#define ABUF_H (BM * LDA)             // 9216 halves
#define BBUF_H (BK * LDB)             // 8704 halves
#define BUF_H  (ABUF_H + BBUF_H)      // 17920 halves (35840 B/stage)
#define NSTAGE 3
#define SMEM_BYTES (NSTAGE * BUF_H * 2)  // 107520 B (covers 75264 B epilogue)

// ---------------- scratch (device globals; no allocs allowed) ----------------
__device__ __half g_he[NTOK * HD];     // encs fp16
__device__ __half g_hw[8 * HD * HD];   // fp16 weights: [0]=fc1 [1]=fc2 [2..7]=ew1
__device__ __half g_t1h[NTOK * HD];    // relu(encs@fc1+b1) fp16
__device__ __half g_xh[NTOK * HD];     // shared-bottom out fp16
__device__ float g_glog[NTOK * 18];    // gate logits, [n][t*6+e]
__device__ float g_s[NTOK * 18];       // h[e,n]·v[e,t], [n][e*3+t]
__device__ float g_v[NE * NT * HD];    // v[e][t][f] = sum_o W2[e,f,o]*tw[t,o]
__device__ float g_c[18];              // c[e*3+t] = tw[t]·b2[e]
__device__ float g_maxs[NB * NT];      // per (b,t) max over candidates
__device__ float g_stats[37];          // [0..17] importance, [18..35] load, [36] bce

// ---------------- cp.async helpers ------------------------------------------
__device__ __forceinline__ uint32_t smem_u32(const void* p) {
    uint32_t a;
    asm("{ .reg .u64 t; cvta.to.shared.u64 t, %1; cvt.u32.u64 %0, t; }"
        : "=r"(a) : "l"(p));
    return a;
}
#define CP16(dst_u32, src) \
    asm volatile("cp.async.cg.shared.global [%0], [%1], 16;" \
                 :: "r"(dst_u32), "l"(src) : "memory")
#define CPCOMMIT() asm volatile("cp.async.commit_group;" ::: "memory")
#define CPWAIT(n)  asm volatile("cp.async.wait_group %0;" :: "n"(n) : "memory")

// ================= fused prep kernel (one launch, block-range dispatch) ======
#define PB_ENCS   0
#define PB_W1     8192
#define PB_W2     9216
#define PB_EW     10240
#define PB_VK     16384
#define PB_ZERO   18688
#define PB_MISC   18976
#define PB_MAXS   18977
#define PREP_BLOCKS 18978

__device__ __forceinline__ void conv4(const float* __restrict__ src,
                                      __half* __restrict__ dst, int base)
{
    int i = base + threadIdx.x * 4;
    float4 v = *(const float4*)(src + i);
    *(__half2*)(dst + i)     = __floats2half2_rn(v.x, v.y);
    *(__half2*)(dst + i + 2) = __floats2half2_rn(v.z, v.w);
}

__global__ __launch_bounds__(256)
void prep_kernel(const float* __restrict__ encs, const float* __restrict__ fc1_w,
                 const float* __restrict__ fc2_w, const float* __restrict__ ew1,
                 const float* __restrict__ ew2, const float* __restrict__ eb2,
                 const float* __restrict__ tw, const float* __restrict__ scores,
                 __half* __restrict__ he, __half* __restrict__ hw,
                 float* __restrict__ glog, float* __restrict__ s,
                 float* __restrict__ stats, float* __restrict__ v,
                 float* __restrict__ c, float* __restrict__ maxs)
{
    const int blk = blockIdx.x;
    const int tid = threadIdx.x;
    const size_t NW = (size_t)HD * HD;

    if (blk < PB_W1) {
        conv4(encs, he, (blk - PB_ENCS) * 1024);
    } else if (blk < PB_W2) {
        conv4(fc1_w, hw, (blk - PB_W1) * 1024);
    } else if (blk < PB_EW) {
        conv4(fc2_w, hw + NW, (blk - PB_W2) * 1024);
    } else if (blk < PB_VK) {
        conv4(ew1, hw + 2 * NW, (blk - PB_EW) * 1024);
    } else if (blk < PB_ZERO) {
        int w = (blk - PB_VK) * 8 + (tid >> 5);
        int lane = tid & 31;
        if (w < NE * NT * HD) {
            int e = w / (NT * HD);
            int r = w % (NT * HD);
            int t = r / HD;
            int f = r % HD;
            const float* row = ew2 + ((size_t)e * HD + f) * HD;
            const float* tv  = tw + (size_t)t * HD;
            float acc = 0.f;
            for (int o = lane; o < HD; o += 32) acc = fmaf(row[o], tv[o], acc);
#pragma unroll
            for (int off = 16; off; off >>= 1)
                acc += __shfl_xor_sync(0xffffffffu, acc, off);
            if (lane == 0) v[w] = acc;
        }
    } else if (blk < PB_MISC) {
        int lb = blk - PB_ZERO;
        float* dst = (lb < 144) ? glog : s;
        int base = (lb % 144) * 1024 + tid * 4;
        *(float4*)(dst + base) = make_float4(0.f, 0.f, 0.f, 0.f);
    } else if (blk == PB_MISC) {
        if (tid < 37) stats[tid] = 0.f;
        int wrp = tid >> 5, lane = tid & 31;
#pragma unroll
        for (int rep = 0; rep < 3; rep++) {
            int j = wrp + rep * 8;
            if (j < 18) {
                int e = j / 3, t = j % 3;
                float acc = 0.f;
                for (int o = lane; o < HD; o += 32)
                    acc = fmaf(eb2[(size_t)e * HD + o], tw[(size_t)t * HD + o], acc);
#pragma unroll
                for (int off = 16; off; off >>= 1)
                    acc += __shfl_xor_sync(0xffffffffu, acc, off);
                if (lane == 0) c[j] = acc;
            }
        }
    } else {
        for (int i = tid; i < NB * NT; i += 256) {
            int b = i / NT, t = i % NT;
            float m = -1e30f;
            for (int cdx = 0; cdx < NC; cdx++)
                m = fmaxf(m, scores[(size_t)b * NC * NT + cdx * NT + t]);
            maxs[i] = m;
        }
    }
}

// ======================= fp16 wmma GEMM ======================================
// CTA 128x128, 8 warps (64x32 each), BK=64, 3-stage cp.async, 2 CTAs/SM
// (16 warps/SM for latency hiding).
// A: half[M,K] row-major.  B: half[K,N] row-major.
// MODE 0: Ch = half(relu(A@B + bias))
// MODE 1: Ch = half(A@B + bias); also glog[n][j] += x[n,:]·wg-slice (fused)
// MODE 2: h = relu(A@B[e] + b1[e]); S[n][e*3+t] += h · v[e][t]  (h not stored)
template <int MODE>
__global__ __launch_bounds__(256, 2)
void wgemm(const __half* __restrict__ A, const __half* __restrict__ B,
           const float* __restrict__ bias, __half* __restrict__ Ch,
           const float* __restrict__ V, float* __restrict__ S,
           const float* __restrict__ WG, float* __restrict__ GL)
{
    extern __shared__ char smraw[];
    __half* sm = (__half*)smraw;
    const int e = blockIdx.z;
    if (MODE == 2) { B += (size_t)e * HD * HD; bias += (size_t)e * HD; }
    const int m0 = blockIdx.y * BM;
    const int n0 = blockIdx.x * BN;
    const int tid = threadIdx.x;
    const int wid = tid >> 5;
    const int wm = wid & 1;        // 64-row slab
    const int wn = wid >> 1;       // 0..3 -> 32-col slab
    const uint32_t sm_u = smem_u32(sm);

    wmma::fragment<wmma::accumulator, 16, 16, 16, float> cf[4][2];
#pragma unroll
    for (int i = 0; i < 4; i++)
#pragma unroll
        for (int j = 0; j < 2; j++) wmma::fill_fragment(cf[i][j], 0.0f);

#define ISSUE_STAGE(st, k0) do {                                              \
        uint32_t base_ = sm_u + (st) * BUF_H * 2;                             \
        uint32_t sa_ = base_, sb_ = base_ + ABUF_H * 2;                       \
        _Pragma("unroll")                                                     \
        for (int j_ = 0; j_ < 4; j_++) {                                      \
            int c_ = tid + 256 * j_;                                          \
            int ar_ = c_ >> 3, ac_ = (c_ & 7) * 8;                            \
            CP16(sa_ + (ar_ * LDA + ac_) * 2,                                 \
                 A + (size_t)(m0 + ar_) * HD + (k0) + ac_);                   \
            int br_ = c_ >> 4, bc_ = (c_ & 15) * 8;                           \
            CP16(sb_ + (br_ * LDB + bc_) * 2,                                 \
                 B + (size_t)((k0) + br_) * HD + n0 + bc_);                   \
        }                                                                     \
        CPCOMMIT();                                                           \
    } while (0)

    ISSUE_STAGE(0, 0);
    ISSUE_STAGE(1, BK);

    for (int kt = 0; kt < KT; kt++) {
        if (kt == KT - 1) { CPWAIT(0); } else { CPWAIT(1); }
        __syncthreads();
        if (kt + 2 < KT) ISSUE_STAGE((kt + 2) % NSTAGE, (kt + 2) * BK);

        const __half* sa = sm + (kt % NSTAGE) * BUF_H;
        const __half* sb = sa + ABUF_H;
        const __half* Abase = sa + (wm * 64) * LDA;
        const __half* Bbase = sb + wn * 32;
#pragma unroll
        for (int kk = 0; kk < 4; kk++) {
            wmma::fragment<wmma::matrix_b, 16, 16, 16, __half, wmma::row_major> bf[2];
#pragma unroll
            for (int j = 0; j < 2; j++)
                wmma::load_matrix_sync(bf[j], Bbase + kk * 16 * LDB + j * 16, LDB);
#pragma unroll
            for (int i = 0; i < 4; i++) {
                wmma::fragment<wmma::matrix_a, 16, 16, 16, __half, wmma::row_major> af;
                wmma::load_matrix_sync(af, Abase + i * 16 * LDA + kk * 16, LDA);
                wmma::mma_sync(cf[i][0], af, bf[0], cf[i][0]);
                wmma::mma_sync(cf[i][1], af, bf[1], cf[i][1]);
            }
        }
    }
#undef ISSUE_STAGE
    __syncthreads();   // stage smem -> epilogue reuse

    // ---- epilogue: accumulators -> smem fp32 C tile (128x128) ----
    float* cb = (float*)smraw;
#pragma unroll
    for (int i = 0; i < 4; i++)
#pragma unroll
        for (int j = 0; j < 2; j++)
            wmma::store_matrix_sync(cb + (wm * 64 + i * 16) * 128 + wn * 32 + j * 16,
                                    cf[i][j], 128, wmma::mem_row_major);

    float* sbias = cb + 128 * 128;           // 128 floats
    if (tid < 128) sbias[tid] = bias[n0 + tid];
    float* sx = sbias + 128;                 // MODE1: wg slice [128][18]; MODE2: v [384]
    if (MODE == 1) {
        for (int idx = tid; idx < 128 * 18; idx += 256) {
            int h = idx / 18, j = idx % 18;
            int t = j / 6, ee = j % 6;
            sx[idx] = WG[(size_t)t * HD * NE + (size_t)(n0 + h) * NE + ee];
        }
    } else if (MODE == 2) {
        for (int j = tid; j < 384; j += 256)
            sx[j] = V[((size_t)e * 3 + (j >> 7)) * HD + n0 + (j & 127)];
    }
    __syncthreads();

    if (MODE < 2) {
#pragma unroll
        for (int j = 0; j < 16; j++) {
            int i = tid + 256 * j;
            int r = i >> 5, col = (i & 31) * 4;
            float v0 = cb[r * 128 + col + 0] + sbias[col + 0];
            float v1 = cb[r * 128 + col + 1] + sbias[col + 1];
            float v2 = cb[r * 128 + col + 2] + sbias[col + 2];
            float v3 = cb[r * 128 + col + 3] + sbias[col + 3];
            if (MODE == 0) {
                v0 = fmaxf(v0, 0.f); v1 = fmaxf(v1, 0.f);
                v2 = fmaxf(v2, 0.f); v3 = fmaxf(v3, 0.f);
            }
            __half* dst = Ch + (size_t)(m0 + r) * HD + n0 + col;
            *(__half2*)(dst)     = __floats2half2_rn(v0, v1);
            *(__half2*)(dst + 2) = __floats2half2_rn(v2, v3);
        }
        if (MODE == 1) {
            // fused gate logits: two threads per row (64 cols each), shfl-combine
            const int r = tid >> 1, h0 = (tid & 1) * 64;
            float acc[18];
#pragma unroll
            for (int j = 0; j < 18; j++) acc[j] = 0.f;
            const float* crow = cb + r * 128 + h0;
            for (int col = 0; col < 64; col++) {
                float xv = crow[col] + sbias[h0 + col];
                const float* ws = sx + (h0 + col) * 18;
#pragma unroll
                for (int j = 0; j < 18; j++) acc[j] = fmaf(xv, ws[j], acc[j]);
            }
#pragma unroll
            for (int j = 0; j < 18; j++)
                acc[j] += __shfl_xor_sync(0xffffffffu, acc[j], 1);
            if (!(tid & 1)) {
                float* gl = GL + (size_t)(m0 + r) * 18;
#pragma unroll
                for (int j = 0; j < 18; j++) atomicAdd(gl + j, acc[j]);
            }
        }
    } else {
        const int r = tid >> 1, h0 = (tid & 1) * 64;
        float p0 = 0.f, p1 = 0.f, p2 = 0.f;
        const float* crow = cb + r * 128 + h0;
#pragma unroll 16
        for (int col = 0; col < 64; col++) {
            float h = fmaxf(crow[col] + sbias[h0 + col], 0.0f);
            p0 = fmaf(h, sx[h0 + col],       p0);
            p1 = fmaf(h, sx[128 + h0 + col], p1);
            p2 = fmaf(h, sx[256 + h0 + col], p2);
        }
        p0 += __shfl_xor_sync(0xffffffffu, p0, 1);
        p1 += __shfl_xor_sync(0xffffffffu, p1, 1);
        p2 += __shfl_xor_sync(0xffffffffu, p2, 1);
        if (!(tid & 1)) {
            float* Sp = S + (size_t)(m0 + r) * 18 + e * 3;
            atomicAdd(Sp + 0, p0);
            atomicAdd(Sp + 1, p1);
            atomicAdd(Sp + 2, p2);
        }
    }
}

// ---------------- per-token: top3/softmax, z, BCE, preds, imp/load ----------
__global__ void token_kernel(const float* __restrict__ glog, const float* __restrict__ s,
                             const float* __restrict__ c, const float* __restrict__ scores,
                             const float* __restrict__ maxs, const float* __restrict__ tb,
                             float* __restrict__ stats, float* __restrict__ preds)
{
    __shared__ float simp[18], sld[18], red[256];
    const int tid = threadIdx.x;
    if (tid < 18) { simp[tid] = 0.f; sld[tid] = 0.f; }
    __syncthreads();

    const int n = blockIdx.x * 256 + tid;
    const int b = n >> 6, cdx = n & 63;

    float l[18];
    const float* gl = glog + (size_t)n * 18;
#pragma unroll
    for (int j = 0; j < 18; j++) l[j] = gl[j];
    const float* sr = s + (size_t)n * 18;

    float bsum = 0.f, zsum = 0.f;
#pragma unroll
    for (int t = 0; t < 3; t++) {
        const float* lt = l + t * 6;
        float sv0 = 0, sv1 = 0, sv2 = 0;
        int se0 = 0, se1 = 0, se2 = 0, cnt = 0;
#pragma unroll
        for (int e = 0; e < 6; e++) {
            int beats = 0;
#pragma unroll
            for (int j = 0; j < 6; j++)
                beats += (lt[j] > lt[e]) || (lt[j] == lt[e] && j < e);
            if (beats < 3) {
                if (cnt == 0)      { sv0 = lt[e]; se0 = e; }
                else if (cnt == 1) { sv1 = lt[e]; se1 = e; }
                else               { sv2 = lt[e]; se2 = e; }
                cnt++;
            }
        }
        float m  = fmaxf(sv0, fmaxf(sv1, sv2));
        float g0 = expf(sv0 - m), g1 = expf(sv1 - m), g2 = expf(sv2 - m);
        float inv = 1.f / (g0 + g1 + g2);
        g0 *= inv; g1 *= inv; g2 *= inv;

        float zt = tb[t];
        zt = fmaf(g0, sr[se0 * 3 + t] + c[se0 * 3 + t], zt);
        zt = fmaf(g1, sr[se1 * 3 + t] + c[se1 * 3 + t], zt);
        zt = fmaf(g2, sr[se2 * 3 + t] + c[se2 * 3 + t], zt);

        atomicAdd(&simp[t * 6 + se0], g0);
        atomicAdd(&simp[t * 6 + se1], g1);
        atomicAdd(&simp[t * 6 + se2], g2);
        atomicAdd(&sld[t * 6 + se0], 1.f);
        atomicAdd(&sld[t * 6 + se1], 1.f);
        atomicAdd(&sld[t * 6 + se2], 1.f);

        float sc  = scores[(size_t)b * NC * NT + cdx * NT + t];
        float lab = (sc == maxs[b * NT + t]) ? 1.f : 0.f;
        bsum += fmaxf(zt, 0.f) - zt * lab + log1pf(expf(-fabsf(zt)));
        zsum += zt;
    }
    preds[n] = 1.f / (1.f + expf(-zsum * (1.f / 3.f)));

    red[tid] = bsum;
    __syncthreads();
    for (int off = 128; off; off >>= 1) {
        if (tid < off) red[tid] += red[tid + off];
        __syncthreads();
    }
    if (tid == 0) atomicAdd(&stats[36], red[0]);
    if (tid < 18) {
        atomicAdd(&stats[tid], simp[tid]);
        atomicAdd(&stats[18 + tid], sld[tid]);
    }
}

// ---------------- final scalar: loss = bce + 1e-2 * sum cv^2 -----------------
__global__ void final_kernel(const float* __restrict__ stats, float* __restrict__ out)
{
    if (threadIdx.x == 0) {
        float aux = 0.f;
        for (int t = 0; t < 3; t++) {
            for (int which = 0; which < 2; which++) {
                const float* v = stats + which * 18 + t * 6;
                float mean = 0.f;
                for (int e = 0; e < 6; e++) mean += v[e];
                mean *= (1.f / 6.f);
                float var = 0.f;
                for (int e = 0; e < 6; e++) {
                    float d = v[e] - mean;
                    var += d * d;
                }
                var *= (1.f / 5.f);
                aux += var / (mean * mean + 1e-10f);
            }
        }
        out[0] = stats[36] * (1.f / (NB * NC * NT)) + 0.01f * aux;
    }
}

// -----------------------------------------------------------------------------
extern "C" void kernel_launch(void* const* d_in, const int* in_sizes, int n_in,
                              void* d_out, int out_size)
{
    const float* encs   = (const float*)d_in[0];
    const float* scores = (const float*)d_in[1];
    const float* fc1_w  = (const float*)d_in[2];
    const float* fc1_b  = (const float*)d_in[3];
    const float* fc2_w  = (const float*)d_in[4];
    const float* fc2_b  = (const float*)d_in[5];
    const float* w_gate = (const float*)d_in[6];
    const float* ew1    = (const float*)d_in[7];
    const float* eb1    = (const float*)d_in[8];
    const float* ew2    = (const float*)d_in[9];
    const float* eb2    = (const float*)d_in[10];
    const float* tw     = (const float*)d_in[11];
    const float* tb     = (const float*)d_in[12];

    __half *he, *hw, *t1h, *xh;
    float *glog, *s, *v, *c, *maxs, *stats;
    cudaGetSymbolAddress((void**)&he, g_he);
    cudaGetSymbolAddress((void**)&hw, g_hw);
    cudaGetSymbolAddress((void**)&t1h, g_t1h);
    cudaGetSymbolAddress((void**)&xh, g_xh);
    cudaGetSymbolAddress((void**)&glog, g_glog);
    cudaGetSymbolAddress((void**)&s, g_s);
    cudaGetSymbolAddress((void**)&v, g_v);
    cudaGetSymbolAddress((void**)&c, g_c);
    cudaGetSymbolAddress((void**)&maxs, g_maxs);
    cudaGetSymbolAddress((void**)&stats, g_stats);

    float* outf  = (float*)d_out;
    float* preds = outf + (out_size - NTOK);

    cudaFuncSetAttribute(wgemm<0>, cudaFuncAttributeMaxDynamicSharedMemorySize, SMEM_BYTES);
    cudaFuncSetAttribute(wgemm<1>, cudaFuncAttributeMaxDynamicSharedMemorySize, SMEM_BYTES);
    cudaFuncSetAttribute(wgemm<2>, cudaFuncAttributeMaxDynamicSharedMemorySize, SMEM_BYTES);

    const size_t NW = (size_t)HD * HD;

    // one fused head launch: conversions + precomputes + zeroing
    prep_kernel<<<PREP_BLOCKS, 256>>>(encs, fc1_w, fc2_w, ew1, ew2, eb2, tw, scores,
                                      he, hw, glog, s, stats, v, c, maxs);

    // shared bottom (fp16 wmma); fc2 fuses gate-logit accumulation
    wgemm<0><<<dim3(8, 64, 1), 256, SMEM_BYTES>>>(he, hw, fc1_b, t1h,
                                                  nullptr, nullptr, nullptr, nullptr);
    wgemm<1><<<dim3(8, 64, 1), 256, SMEM_BYTES>>>(t1h, hw + NW, fc2_b, xh,
                                                  nullptr, nullptr, w_gate, glog);
    // experts: layer-1 GEMM fused with tower-projected reduction (layer-2 eliminated)
    wgemm<2><<<dim3(8, 64, 6), 256, SMEM_BYTES>>>(xh, hw + 2 * NW, eb1, nullptr,
                                                  v, s, nullptr, nullptr);
    // per-token gating + loss + preds
    token_kernel<<<32, 256>>>(glog, s, c, scores, maxs, tb, stats, preds);
    if (out_size > NTOK) final_kernel<<<1, 32>>>(stats, outf);
}